// round 1
// baseline (speedup 1.0000x reference)
#include <cuda_runtime.h>

#define NB   16
#define C    64
#define HH   96
#define WW   96
#define HWSZ (HH * WW)        // 9216
#define CHW  (C * HWSZ)       // 589824
#define KK   576              // C * 9

// Scratch (static device arrays — no allocation in kernel_launch)
__device__ float g_kf[NB * CHW];
__device__ float g_qf[NB * CHW];
__device__ float g_vf[NB * CHW];
__device__ float g_attn[NB * C * KK];

// Blackwell packed fp32 FMA: d = a*b + c on both lanes (SASS FFMA2)
__device__ __forceinline__ float2 ffma2(float2 a, float2 b, float2 c) {
    unsigned long long ua = reinterpret_cast<unsigned long long&>(a);
    unsigned long long ub = reinterpret_cast<unsigned long long&>(b);
    unsigned long long uc = reinterpret_cast<unsigned long long&>(c);
    asm("fma.rn.f32x2 %0, %1, %2, %0;" : "+l"(uc) : "l"(ua), "l"(ub));
    return reinterpret_cast<float2&>(uc);
}

// ---------------------------------------------------------------------------
// 3x3 conv, 64->64 channels, pad 1, cross-correlation (JAX conv semantics).
// Output tile: 64 couts x (8 rows x 16 cols) pixels. Block = 256 threads.
// Thread tile: 8 couts x 4 pixels, accumulated as 4x4 float2 (cout pairs).
// which: 0 -> y=g_kf, 1 -> y=g_qf, 2 -> y=g_vf,
//        3 -> dynamic conv: x=g_vf, w=g_attn (per-batch), y=param y (d_out)
// ---------------------------------------------------------------------------
__global__ void __launch_bounds__(256) conv3x3_kernel(
    const float* __restrict__ x, const float* __restrict__ w,
    float* __restrict__ y, int which)
{
    const int tile = blockIdx.x;            // 0..71
    const int b    = blockIdx.y;            // 0..15
    const int row0 = (tile / 6) * 8;
    const int col0 = (tile % 6) * 16;

    const float* xp = x;
    const float* wp = w;
    float*       yp = y;
    bool per_batch_w = false;
    if (which == 0)      yp = g_kf;
    else if (which == 1) yp = g_qf;
    else if (which == 2) yp = g_vf;
    else { xp = g_vf; wp = g_attn; per_batch_w = true; }

    const float* xb = xp + (size_t)b * CHW;
    const float* wb = per_batch_w ? (wp + (size_t)b * C * KK) : wp;
    float*       yb = yp + (size_t)b * CHW;

    __shared__ float SW[72][68];     // [k = ci*9 + kh*3 + kw][cout], padded
    __shared__ float SI[8][10][21];  // [ci][row (-1..8)][col (-1..16)], padded

    const int tid = threadIdx.x;
    const int tx  = tid & 31;        // pixel group
    const int ty  = tid >> 5;        // cout group (warp-uniform -> SW broadcast)
    const int pr  = tx >> 2;         // tile row 0..7
    const int pc  = (tx & 3) << 2;   // tile col base 0,4,8,12

    float2 acc[4][4];
    #pragma unroll
    for (int i = 0; i < 4; i++)
        #pragma unroll
        for (int j = 0; j < 4; j++) acc[i][j] = make_float2(0.f, 0.f);

    for (int ci0 = 0; ci0 < C; ci0 += 8) {
        __syncthreads();
        // weights chunk: 64 couts x 72 k  (4608 = 18*256, exact)
        #pragma unroll
        for (int it = 0; it < 18; it++) {
            int idx  = tid + it * 256;
            int cout = idx / 72;
            int r    = idx - cout * 72;
            SW[r][cout] = wb[cout * KK + ci0 * 9 + r];
        }
        // input chunk: 8 cin x 10 x 18 halo tile (1440 elems), zero-padded
        #pragma unroll
        for (int it = 0; it < 6; it++) {
            int idx = tid + it * 256;
            if (idx < 1440) {
                int ci  = idx / 180;
                int rem = idx - ci * 180;
                int r   = rem / 18;
                int cc  = rem - r * 18;
                int gr  = row0 + r - 1;
                int gc  = col0 + cc - 1;
                float v = 0.f;
                if ((unsigned)gr < 96u && (unsigned)gc < 96u)
                    v = xb[(ci0 + ci) * HWSZ + gr * WW + gc];
                SI[ci][r][cc] = v;
            }
        }
        __syncthreads();

        #pragma unroll 2
        for (int ci = 0; ci < 8; ci++) {
            #pragma unroll
            for (int kh = 0; kh < 3; kh++) {
                #pragma unroll
                for (int kw = 0; kw < 3; kw++) {
                    const int k = ci * 9 + kh * 3 + kw;
                    const float2* ap =
                        reinterpret_cast<const float2*>(&SW[k][ty * 8]);
                    float2 a0 = ap[0], a1 = ap[1], a2 = ap[2], a3 = ap[3];
                    const float* bp = &SI[ci][pr + kh][pc + kw];
                    float s0 = bp[0], s1 = bp[1], s2 = bp[2], s3 = bp[3];
                    float2 b0 = make_float2(s0, s0);
                    float2 b1 = make_float2(s1, s1);
                    float2 b2 = make_float2(s2, s2);
                    float2 b3 = make_float2(s3, s3);
                    acc[0][0] = ffma2(a0, b0, acc[0][0]);
                    acc[0][1] = ffma2(a0, b1, acc[0][1]);
                    acc[0][2] = ffma2(a0, b2, acc[0][2]);
                    acc[0][3] = ffma2(a0, b3, acc[0][3]);
                    acc[1][0] = ffma2(a1, b0, acc[1][0]);
                    acc[1][1] = ffma2(a1, b1, acc[1][1]);
                    acc[1][2] = ffma2(a1, b2, acc[1][2]);
                    acc[1][3] = ffma2(a1, b3, acc[1][3]);
                    acc[2][0] = ffma2(a2, b0, acc[2][0]);
                    acc[2][1] = ffma2(a2, b1, acc[2][1]);
                    acc[2][2] = ffma2(a2, b2, acc[2][2]);
                    acc[2][3] = ffma2(a2, b3, acc[2][3]);
                    acc[3][0] = ffma2(a3, b0, acc[3][0]);
                    acc[3][1] = ffma2(a3, b1, acc[3][1]);
                    acc[3][2] = ffma2(a3, b2, acc[3][2]);
                    acc[3][3] = ffma2(a3, b3, acc[3][3]);
                }
            }
        }
    }

    #pragma unroll
    for (int cp = 0; cp < 4; cp++) {
        int cout = ty * 8 + cp * 2;
        float4 v0 = make_float4(acc[cp][0].x, acc[cp][1].x,
                                acc[cp][2].x, acc[cp][3].x);
        float4 v1 = make_float4(acc[cp][0].y, acc[cp][1].y,
                                acc[cp][2].y, acc[cp][3].y);
        float* o = yb + cout * HWSZ + (row0 + pr) * WW + col0 + pc;
        *reinterpret_cast<float4*>(o)        = v0;
        *reinterpret_cast<float4*>(o + HWSZ) = v1;
    }
}

// ---------------------------------------------------------------------------
// scores[b,k,c,d] = sum over 1024 sub-lattice pixels of kf[b,c,*] * qf[b,d,*]
// written as attn[b, d, c*9 + k] / 24 (pre-softmax).
// Grid (9, 16), block 256, 64x64 output, K=1024 in chunks of 32.
// ---------------------------------------------------------------------------
__global__ void __launch_bounds__(256) scores_kernel()
{
    const int k  = blockIdx.x;   // 0..8
    const int b  = blockIdx.y;   // 0..15
    const int kh = k / 3, kw = k % 3;
    const float* kfb = g_kf + (size_t)b * CHW;
    const float* qfb = g_qf + (size_t)b * CHW;

    __shared__ float SK[32][68];  // [li][c]
    __shared__ float SQ[32][68];  // [li][d]

    const int tid = threadIdx.x;
    const int tc  = (tid & 15) << 2;  // key-channel block
    const int td  = (tid >> 4) << 2;  // query-channel block

    float acc[4][4] = {};

    for (int l0 = 0; l0 < 1024; l0 += 32) {
        __syncthreads();
        #pragma unroll
        for (int it = 0; it < 8; it++) {
            int idx = tid + it * 256;       // 0..2047
            int c   = idx >> 5;
            int li  = idx & 31;
            int l   = l0 + li;
            int pix = (3 * (l >> 5) + kh) * WW + 3 * (l & 31) + kw;
            SK[li][c] = kfb[c * HWSZ + pix];
            SQ[li][c] = qfb[c * HWSZ + pix];
        }
        __syncthreads();
        #pragma unroll 8
        for (int li = 0; li < 32; li++) {
            float4 av = *reinterpret_cast<const float4*>(&SK[li][tc]);
            float4 bv = *reinterpret_cast<const float4*>(&SQ[li][td]);
            float a[4]  = {av.x, av.y, av.z, av.w};
            float bb[4] = {bv.x, bv.y, bv.z, bv.w};
            #pragma unroll
            for (int i = 0; i < 4; i++)
                #pragma unroll
                for (int j = 0; j < 4; j++)
                    acc[i][j] = fmaf(a[i], bb[j], acc[i][j]);
        }
    }

    const float sc = 1.0f / 24.0f;  // 1/sqrt(64*9)
    #pragma unroll
    for (int j = 0; j < 4; j++) {
        float* ap = g_attn + ((size_t)(b * C + td + j)) * KK + k;
        #pragma unroll
        for (int i = 0; i < 4; i++)
            ap[(tc + i) * 9] = acc[i][j] * sc;
    }
}

// ---------------------------------------------------------------------------
// Softmax over 576 entries per (b, d) row, in place. One warp per row.
// ---------------------------------------------------------------------------
__global__ void __launch_bounds__(256) softmax_kernel()
{
    const int row  = blockIdx.x * 8 + (threadIdx.x >> 5);  // 0..1023
    const int lane = threadIdx.x & 31;
    float* p = g_attn + (size_t)row * KK;

    float v[18];
    float m = -3.4e38f;
    #pragma unroll
    for (int i = 0; i < 18; i++) { v[i] = p[lane + i * 32]; m = fmaxf(m, v[i]); }
    #pragma unroll
    for (int o = 16; o > 0; o >>= 1)
        m = fmaxf(m, __shfl_xor_sync(0xffffffffu, m, o));
    float s = 0.f;
    #pragma unroll
    for (int i = 0; i < 18; i++) { v[i] = __expf(v[i] - m); s += v[i]; }
    #pragma unroll
    for (int o = 16; o > 0; o >>= 1)
        s += __shfl_xor_sync(0xffffffffu, s, o);
    float inv = 1.0f / s;
    #pragma unroll
    for (int i = 0; i < 18; i++) p[lane + i * 32] = v[i] * inv;
}

extern "C" void kernel_launch(void* const* d_in, const int* in_sizes, int n_in,
                              void* d_out, int out_size)
{
    const float* x1 = (const float*)d_in[0];
    const float* x2 = (const float*)d_in[1];
    const float* w1 = (const float*)d_in[2];
    const float* w2 = (const float*)d_in[3];
    const float* w3 = (const float*)d_in[4];
    float* out = (float*)d_out;

    dim3 cgrid(72, 16);
    conv3x3_kernel<<<cgrid, 256>>>(x1, w1, nullptr, 0);   // kf
    conv3x3_kernel<<<cgrid, 256>>>(x2, w2, nullptr, 1);   // qf
    conv3x3_kernel<<<cgrid, 256>>>(x1, w3, nullptr, 2);   // vf
    scores_kernel<<<dim3(9, 16), 256>>>();
    softmax_kernel<<<128, 256>>>();
    conv3x3_kernel<<<cgrid, 256>>>(nullptr, nullptr, out, 3);  // dynamic conv
}

// round 2
// speedup vs baseline: 1.0010x; 1.0010x over previous
#include <cuda_runtime.h>

#define NB   16
#define C    64
#define HH   96
#define WW   96
#define HWSZ (HH * WW)        // 9216
#define CHW  (C * HWSZ)       // 589824
#define KK   576              // C * 9

// Scratch (static device arrays — no allocation in kernel_launch)
__device__ float g_kf[NB * CHW];
__device__ float g_qf[NB * CHW];
__device__ float g_vf[NB * CHW];
__device__ float g_attn[NB * C * KK];

// Blackwell packed fp32 FMA: d = a*b + c on both lanes (SASS FFMA2)
__device__ __forceinline__ float2 ffma2(float2 a, float2 b, float2 c) {
    unsigned long long ua = reinterpret_cast<unsigned long long&>(a);
    unsigned long long ub = reinterpret_cast<unsigned long long&>(b);
    unsigned long long uc = reinterpret_cast<unsigned long long&>(c);
    asm("fma.rn.f32x2 %0, %1, %2, %0;" : "+l"(uc) : "l"(ua), "l"(ub));
    return reinterpret_cast<float2&>(uc);
}

// ---------------------------------------------------------------------------
// 3x3 conv, 64->64 channels, pad 1, cross-correlation (JAX conv semantics).
// Output tile: 64 couts x (8 rows x 16 cols) pixels. Block = 256 threads.
// Thread tile: 8 couts x 4 pixels, accumulated as 4x4 float2 (cout pairs).
// which: 0 -> y=g_kf, 1 -> y=g_qf, 2 -> y=g_vf,
//        3 -> dynamic conv: x=g_vf, w=g_attn (per-batch), y=param y (d_out)
// ---------------------------------------------------------------------------
__global__ void __launch_bounds__(256) conv3x3_kernel(
    const float* __restrict__ x, const float* __restrict__ w,
    float* __restrict__ y, int which)
{
    const int tile = blockIdx.x;            // 0..71
    const int b    = blockIdx.y;            // 0..15
    const int row0 = (tile / 6) * 8;
    const int col0 = (tile % 6) * 16;

    const float* xp = x;
    const float* wp = w;
    float*       yp = y;
    bool per_batch_w = false;
    if (which == 0)      yp = g_kf;
    else if (which == 1) yp = g_qf;
    else if (which == 2) yp = g_vf;
    else { xp = g_vf; wp = g_attn; per_batch_w = true; }

    const float* xb = xp + (size_t)b * CHW;
    const float* wb = per_batch_w ? (wp + (size_t)b * C * KK) : wp;
    float*       yb = yp + (size_t)b * CHW;

    __shared__ float SW[72][68];     // [k = ci*9 + kh*3 + kw][cout], padded
    __shared__ float SI[8][10][21];  // [ci][row (-1..8)][col (-1..16)], padded

    const int tid = threadIdx.x;
    const int tx  = tid & 31;        // pixel group
    const int ty  = tid >> 5;        // cout group (warp-uniform -> SW broadcast)
    const int pr  = tx >> 2;         // tile row 0..7
    const int pc  = (tx & 3) << 2;   // tile col base 0,4,8,12

    float2 acc[4][4];
    #pragma unroll
    for (int i = 0; i < 4; i++)
        #pragma unroll
        for (int j = 0; j < 4; j++) acc[i][j] = make_float2(0.f, 0.f);

    for (int ci0 = 0; ci0 < C; ci0 += 8) {
        __syncthreads();
        // weights chunk: 64 couts x 72 k  (4608 = 18*256, exact)
        #pragma unroll
        for (int it = 0; it < 18; it++) {
            int idx  = tid + it * 256;
            int cout = idx / 72;
            int r    = idx - cout * 72;
            SW[r][cout] = wb[cout * KK + ci0 * 9 + r];
        }
        // input chunk: 8 cin x 10 x 18 halo tile (1440 elems), zero-padded
        #pragma unroll
        for (int it = 0; it < 6; it++) {
            int idx = tid + it * 256;
            if (idx < 1440) {
                int ci  = idx / 180;
                int rem = idx - ci * 180;
                int r   = rem / 18;
                int cc  = rem - r * 18;
                int gr  = row0 + r - 1;
                int gc  = col0 + cc - 1;
                float v = 0.f;
                if ((unsigned)gr < 96u && (unsigned)gc < 96u)
                    v = xb[(ci0 + ci) * HWSZ + gr * WW + gc];
                SI[ci][r][cc] = v;
            }
        }
        __syncthreads();

        #pragma unroll 2
        for (int ci = 0; ci < 8; ci++) {
            #pragma unroll
            for (int kh = 0; kh < 3; kh++) {
                #pragma unroll
                for (int kw = 0; kw < 3; kw++) {
                    const int k = ci * 9 + kh * 3 + kw;
                    const float2* ap =
                        reinterpret_cast<const float2*>(&SW[k][ty * 8]);
                    float2 a0 = ap[0], a1 = ap[1], a2 = ap[2], a3 = ap[3];
                    const float* bp = &SI[ci][pr + kh][pc + kw];
                    float s0 = bp[0], s1 = bp[1], s2 = bp[2], s3 = bp[3];
                    float2 b0 = make_float2(s0, s0);
                    float2 b1 = make_float2(s1, s1);
                    float2 b2 = make_float2(s2, s2);
                    float2 b3 = make_float2(s3, s3);
                    acc[0][0] = ffma2(a0, b0, acc[0][0]);
                    acc[0][1] = ffma2(a0, b1, acc[0][1]);
                    acc[0][2] = ffma2(a0, b2, acc[0][2]);
                    acc[0][3] = ffma2(a0, b3, acc[0][3]);
                    acc[1][0] = ffma2(a1, b0, acc[1][0]);
                    acc[1][1] = ffma2(a1, b1, acc[1][1]);
                    acc[1][2] = ffma2(a1, b2, acc[1][2]);
                    acc[1][3] = ffma2(a1, b3, acc[1][3]);
                    acc[2][0] = ffma2(a2, b0, acc[2][0]);
                    acc[2][1] = ffma2(a2, b1, acc[2][1]);
                    acc[2][2] = ffma2(a2, b2, acc[2][2]);
                    acc[2][3] = ffma2(a2, b3, acc[2][3]);
                    acc[3][0] = ffma2(a3, b0, acc[3][0]);
                    acc[3][1] = ffma2(a3, b1, acc[3][1]);
                    acc[3][2] = ffma2(a3, b2, acc[3][2]);
                    acc[3][3] = ffma2(a3, b3, acc[3][3]);
                }
            }
        }
    }

    #pragma unroll
    for (int cp = 0; cp < 4; cp++) {
        int cout = ty * 8 + cp * 2;
        float4 v0 = make_float4(acc[cp][0].x, acc[cp][1].x,
                                acc[cp][2].x, acc[cp][3].x);
        float4 v1 = make_float4(acc[cp][0].y, acc[cp][1].y,
                                acc[cp][2].y, acc[cp][3].y);
        float* o = yb + cout * HWSZ + (row0 + pr) * WW + col0 + pc;
        *reinterpret_cast<float4*>(o)        = v0;
        *reinterpret_cast<float4*>(o + HWSZ) = v1;
    }
}

// ---------------------------------------------------------------------------
// scores[b,k,c,d] = sum over 1024 sub-lattice pixels of kf[b,c,*] * qf[b,d,*]
// written as attn[b, d, c*9 + k] / 24 (pre-softmax).
// Grid (9, 16), block 256, 64x64 output, K=1024 in chunks of 32.
// ---------------------------------------------------------------------------
__global__ void __launch_bounds__(256) scores_kernel()
{
    const int k  = blockIdx.x;   // 0..8
    const int b  = blockIdx.y;   // 0..15
    const int kh = k / 3, kw = k % 3;
    const float* kfb = g_kf + (size_t)b * CHW;
    const float* qfb = g_qf + (size_t)b * CHW;

    __shared__ float SK[32][68];  // [li][c]
    __shared__ float SQ[32][68];  // [li][d]

    const int tid = threadIdx.x;
    const int tc  = (tid & 15) << 2;  // key-channel block
    const int td  = (tid >> 4) << 2;  // query-channel block

    float acc[4][4] = {};

    for (int l0 = 0; l0 < 1024; l0 += 32) {
        __syncthreads();
        #pragma unroll
        for (int it = 0; it < 8; it++) {
            int idx = tid + it * 256;       // 0..2047
            int c   = idx >> 5;
            int li  = idx & 31;
            int l   = l0 + li;
            int pix = (3 * (l >> 5) + kh) * WW + 3 * (l & 31) + kw;
            SK[li][c] = kfb[c * HWSZ + pix];
            SQ[li][c] = qfb[c * HWSZ + pix];
        }
        __syncthreads();
        #pragma unroll 8
        for (int li = 0; li < 32; li++) {
            float4 av = *reinterpret_cast<const float4*>(&SK[li][tc]);
            float4 bv = *reinterpret_cast<const float4*>(&SQ[li][td]);
            float a[4]  = {av.x, av.y, av.z, av.w};
            float bb[4] = {bv.x, bv.y, bv.z, bv.w};
            #pragma unroll
            for (int i = 0; i < 4; i++)
                #pragma unroll
                for (int j = 0; j < 4; j++)
                    acc[i][j] = fmaf(a[i], bb[j], acc[i][j]);
        }
    }

    const float sc = 1.0f / 24.0f;  // 1/sqrt(64*9)
    #pragma unroll
    for (int j = 0; j < 4; j++) {
        float* ap = g_attn + ((size_t)(b * C + td + j)) * KK + k;
        #pragma unroll
        for (int i = 0; i < 4; i++)
            ap[(tc + i) * 9] = acc[i][j] * sc;
    }
}

// ---------------------------------------------------------------------------
// Softmax over 576 entries per (b, d) row, in place. One warp per row.
// ---------------------------------------------------------------------------
__global__ void __launch_bounds__(256) softmax_kernel()
{
    const int row  = blockIdx.x * 8 + (threadIdx.x >> 5);  // 0..1023
    const int lane = threadIdx.x & 31;
    float* p = g_attn + (size_t)row * KK;

    float v[18];
    float m = -3.4e38f;
    #pragma unroll
    for (int i = 0; i < 18; i++) { v[i] = p[lane + i * 32]; m = fmaxf(m, v[i]); }
    #pragma unroll
    for (int o = 16; o > 0; o >>= 1)
        m = fmaxf(m, __shfl_xor_sync(0xffffffffu, m, o));
    float s = 0.f;
    #pragma unroll
    for (int i = 0; i < 18; i++) { v[i] = __expf(v[i] - m); s += v[i]; }
    #pragma unroll
    for (int o = 16; o > 0; o >>= 1)
        s += __shfl_xor_sync(0xffffffffu, s, o);
    float inv = 1.0f / s;
    #pragma unroll
    for (int i = 0; i < 18; i++) p[lane + i * 32] = v[i] * inv;
}

extern "C" void kernel_launch(void* const* d_in, const int* in_sizes, int n_in,
                              void* d_out, int out_size)
{
    const float* x1 = (const float*)d_in[0];
    const float* x2 = (const float*)d_in[1];
    const float* w1 = (const float*)d_in[2];
    const float* w2 = (const float*)d_in[3];
    const float* w3 = (const float*)d_in[4];
    float* out = (float*)d_out;

    dim3 cgrid(72, 16);
    conv3x3_kernel<<<cgrid, 256>>>(x1, w1, nullptr, 0);   // kf
    conv3x3_kernel<<<cgrid, 256>>>(x2, w2, nullptr, 1);   // qf
    conv3x3_kernel<<<cgrid, 256>>>(x1, w3, nullptr, 2);   // vf
    scores_kernel<<<dim3(9, 16), 256>>>();
    softmax_kernel<<<128, 256>>>();
    conv3x3_kernel<<<cgrid, 256>>>(nullptr, nullptr, out, 3);  // dynamic conv
}

// round 3
// speedup vs baseline: 1.1934x; 1.1922x over previous
#include <cuda_runtime.h>

#define NB   16
#define C    64
#define HH   96
#define WW   96
#define HWSZ (HH * WW)        // 9216
#define CHW  (C * HWSZ)       // 589824
#define KK   576              // C * 9
#define NSLICE 4

// Scratch (static device arrays — no allocation in kernel_launch)
__device__ float g_kf[NB * CHW];
__device__ float g_qf[NB * CHW];
__device__ float g_vf[NB * CHW];
__device__ float g_attn[NB * C * KK];
__device__ float g_sc[NSLICE][NB * C * KK];   // partial scores per K-slice

// Blackwell packed fp32 FMA: d = a*b + c on both lanes (SASS FFMA2)
__device__ __forceinline__ float2 ffma2(float2 a, float2 b, float2 c) {
    unsigned long long ua = reinterpret_cast<unsigned long long&>(a);
    unsigned long long ub = reinterpret_cast<unsigned long long&>(b);
    unsigned long long uc = reinterpret_cast<unsigned long long&>(c);
    asm("fma.rn.f32x2 %0, %1, %2, %0;" : "+l"(uc) : "l"(ua), "l"(ub));
    return reinterpret_cast<float2&>(uc);
}

// ---------------------------------------------------------------------------
// 3x3 conv, 64->64 ch, pad 1, cross-correlation.
// Tile: 64 cout x (16x16 px). Block 256 threads, thread tile 8 cout x 8 px.
// A (weights) via warp-broadcast LDS.128; B (pixels) via 3 aligned LDS.128
// per (ci,kh) covering all 3 kw windows.  2 CTAs/SM.
// dyn==0: blockIdx.z picks (x1,w1->kf),(x2,w2->qf),(x1,w3->vf)
// dyn==1: x=g_vf, w=g_attn[b], y=out
// ---------------------------------------------------------------------------
__global__ void __launch_bounds__(256, 2) conv3x3_kernel(
    const float* __restrict__ x1, const float* __restrict__ x2,
    const float* __restrict__ w1, const float* __restrict__ w2,
    const float* __restrict__ w3, float* __restrict__ out, int dyn)
{
    const int tile = blockIdx.x;            // 0..35
    const int b    = blockIdx.y;            // 0..15
    const int row0 = (tile / 6) * 16;
    const int col0 = (tile % 6) * 16;

    const float* xp;
    const float* wp;
    float*       yp;
    bool per_batch_w = false;
    if (dyn) { xp = g_vf; wp = g_attn; yp = out; per_batch_w = true; }
    else if (blockIdx.z == 0) { xp = x1; wp = w1; yp = g_kf; }
    else if (blockIdx.z == 1) { xp = x2; wp = w2; yp = g_qf; }
    else                      { xp = x1; wp = w3; yp = g_vf; }

    const float* xb = xp + (size_t)b * CHW;
    const float* wb = per_batch_w ? (wp + (size_t)b * C * KK) : wp;
    float*       yb = yp + (size_t)b * CHW;

    __shared__ float SW[72][68];        // [k = ci*9 + kh*3 + kw][cout]
    __shared__ float SI[8][18][20];     // [ci][row -1..16][col -1..16], padded

    const int tid = threadIdx.x;
    const int tx  = tid & 31;           // pixel group (within warp)
    const int ty  = tid >> 5;           // cout group (warp-uniform)
    const int pr  = tx & 15;            // out row in tile 0..15
    const int ph  = tx >> 4;            // col half: 0 or 1 (8 px each)

    float2 acc[4][8];
    #pragma unroll
    for (int i = 0; i < 4; i++)
        #pragma unroll
        for (int j = 0; j < 8; j++) acc[i][j] = make_float2(0.f, 0.f);

    for (int ci0 = 0; ci0 < C; ci0 += 8) {
        __syncthreads();
        // weights chunk: 64 couts x 72 k  (4608 = 18*256)
        #pragma unroll
        for (int it = 0; it < 18; it++) {
            int idx  = tid + it * 256;
            int cout = idx / 72;
            int r    = idx - cout * 72;
            SW[r][cout] = wb[cout * KK + ci0 * 9 + r];
        }
        // input chunk: 8 cin x 18 x 18 halo tile (2592 elems), zero-padded
        #pragma unroll
        for (int it = 0; it < 11; it++) {
            int idx = tid + it * 256;
            if (idx < 2592) {
                int ci  = idx / 324;
                int rem = idx - ci * 324;
                int rr  = rem / 18;
                int cc  = rem - rr * 18;
                int gr  = row0 + rr - 1;
                int gc  = col0 + cc - 1;
                float v = 0.f;
                if ((unsigned)gr < 96u && (unsigned)gc < 96u)
                    v = xb[(ci0 + ci) * HWSZ + gr * WW + gc];
                SI[ci][rr][cc] = v;
            }
        }
        __syncthreads();

        #pragma unroll
        for (int ci = 0; ci < 8; ci++) {
            #pragma unroll
            for (int kh = 0; kh < 3; kh++) {
                // 12-float window (cols ph*8 .. ph*8+11), aligned LDS.128 x3
                const float* bp = &SI[ci][pr + kh][ph * 8];
                float4 q0 = *reinterpret_cast<const float4*>(bp);
                float4 q1 = *reinterpret_cast<const float4*>(bp + 4);
                float4 q2 = *reinterpret_cast<const float4*>(bp + 8);
                float bw[12] = {q0.x, q0.y, q0.z, q0.w,
                                q1.x, q1.y, q1.z, q1.w,
                                q2.x, q2.y, q2.z, q2.w};
                float2 bd[10];
                #pragma unroll
                for (int t = 0; t < 10; t++)
                    bd[t] = make_float2(bw[t], bw[t]);

                #pragma unroll
                for (int kw = 0; kw < 3; kw++) {
                    const int k = ci * 9 + kh * 3 + kw;
                    // warp-broadcast weight reads (ty uniform in warp)
                    float4 a01 = *reinterpret_cast<const float4*>(&SW[k][ty * 8]);
                    float4 a23 = *reinterpret_cast<const float4*>(&SW[k][ty * 8 + 4]);
                    float2 a[4] = {make_float2(a01.x, a01.y),
                                   make_float2(a01.z, a01.w),
                                   make_float2(a23.x, a23.y),
                                   make_float2(a23.z, a23.w)};
                    #pragma unroll
                    for (int i = 0; i < 4; i++)
                        #pragma unroll
                        for (int j = 0; j < 8; j++)
                            acc[i][j] = ffma2(a[i], bd[kw + j], acc[i][j]);
                }
            }
        }
    }

    #pragma unroll
    for (int i = 0; i < 4; i++) {
        int cout = ty * 8 + i * 2;
        float* o = yb + (size_t)cout * HWSZ + (row0 + pr) * WW + col0 + ph * 8;
        float4 lo0 = make_float4(acc[i][0].x, acc[i][1].x, acc[i][2].x, acc[i][3].x);
        float4 lo1 = make_float4(acc[i][4].x, acc[i][5].x, acc[i][6].x, acc[i][7].x);
        float4 hi0 = make_float4(acc[i][0].y, acc[i][1].y, acc[i][2].y, acc[i][3].y);
        float4 hi1 = make_float4(acc[i][4].y, acc[i][5].y, acc[i][6].y, acc[i][7].y);
        *reinterpret_cast<float4*>(o)            = lo0;
        *reinterpret_cast<float4*>(o + 4)        = lo1;
        *reinterpret_cast<float4*>(o + HWSZ)     = hi0;
        *reinterpret_cast<float4*>(o + HWSZ + 4) = hi1;
    }
}

// ---------------------------------------------------------------------------
// scores partials: slice s covers L in [s*256, s*256+256).
// g_sc[s][b*64+d][c*9+k] = (1/24) * sum_L kf[b,c,pix]*qf[b,d,pix]
// Grid (9, 16, 4), block 256.
// ---------------------------------------------------------------------------
__global__ void __launch_bounds__(256) scores_kernel()
{
    const int k  = blockIdx.x;   // 0..8
    const int b  = blockIdx.y;   // 0..15
    const int s  = blockIdx.z;   // 0..3
    const int kh = k / 3, kw = k % 3;
    const float* kfb = g_kf + (size_t)b * CHW;
    const float* qfb = g_qf + (size_t)b * CHW;

    __shared__ float SK[32][68];
    __shared__ float SQ[32][68];

    const int tid = threadIdx.x;
    const int tc  = (tid & 15) << 2;
    const int td  = (tid >> 4) << 2;

    float acc[4][4] = {};

    for (int l0 = s * 256; l0 < s * 256 + 256; l0 += 32) {
        __syncthreads();
        #pragma unroll
        for (int it = 0; it < 8; it++) {
            int idx = tid + it * 256;       // 0..2047
            int c   = idx >> 5;
            int li  = idx & 31;
            int l   = l0 + li;
            int pix = (3 * (l >> 5) + kh) * WW + 3 * (l & 31) + kw;
            SK[li][c] = kfb[c * HWSZ + pix];
            SQ[li][c] = qfb[c * HWSZ + pix];
        }
        __syncthreads();
        #pragma unroll 8
        for (int li = 0; li < 32; li++) {
            float4 av = *reinterpret_cast<const float4*>(&SK[li][tc]);
            float4 bv = *reinterpret_cast<const float4*>(&SQ[li][td]);
            float a[4]  = {av.x, av.y, av.z, av.w};
            float bb[4] = {bv.x, bv.y, bv.z, bv.w};
            #pragma unroll
            for (int i = 0; i < 4; i++)
                #pragma unroll
                for (int j = 0; j < 4; j++)
                    acc[i][j] = fmaf(a[i], bb[j], acc[i][j]);
        }
    }

    const float sc = 1.0f / 24.0f;  // 1/sqrt(64*9)
    #pragma unroll
    for (int j = 0; j < 4; j++) {
        float* ap = g_sc[s] + ((size_t)(b * C + td + j)) * KK + k;
        #pragma unroll
        for (int i = 0; i < 4; i++)
            ap[(tc + i) * 9] = acc[i][j] * sc;
    }
}

// ---------------------------------------------------------------------------
// Reduce 4 partial slices + softmax over 576 per (b,d) row -> g_attn.
// One warp per row.
// ---------------------------------------------------------------------------
__global__ void __launch_bounds__(256) softmax_kernel()
{
    const int row  = blockIdx.x * 8 + (threadIdx.x >> 5);  // 0..1023
    const int lane = threadIdx.x & 31;
    const size_t off = (size_t)row * KK;

    float v[18];
    float m = -3.4e38f;
    #pragma unroll
    for (int i = 0; i < 18; i++) {
        int idx = lane + i * 32;
        float t = g_sc[0][off + idx] + g_sc[1][off + idx]
                + g_sc[2][off + idx] + g_sc[3][off + idx];
        v[i] = t;
        m = fmaxf(m, t);
    }
    #pragma unroll
    for (int o = 16; o > 0; o >>= 1)
        m = fmaxf(m, __shfl_xor_sync(0xffffffffu, m, o));
    float ssum = 0.f;
    #pragma unroll
    for (int i = 0; i < 18; i++) { v[i] = __expf(v[i] - m); ssum += v[i]; }
    #pragma unroll
    for (int o = 16; o > 0; o >>= 1)
        ssum += __shfl_xor_sync(0xffffffffu, ssum, o);
    float inv = 1.0f / ssum;
    #pragma unroll
    for (int i = 0; i < 18; i++) g_attn[off + lane + i * 32] = v[i] * inv;
}

extern "C" void kernel_launch(void* const* d_in, const int* in_sizes, int n_in,
                              void* d_out, int out_size)
{
    const float* x1 = (const float*)d_in[0];
    const float* x2 = (const float*)d_in[1];
    const float* w1 = (const float*)d_in[2];
    const float* w2 = (const float*)d_in[3];
    const float* w3 = (const float*)d_in[4];
    float* out = (float*)d_out;

    conv3x3_kernel<<<dim3(36, 16, 3), 256>>>(x1, x2, w1, w2, w3, out, 0);
    scores_kernel<<<dim3(9, 16, NSLICE), 256>>>();
    softmax_kernel<<<128, 256>>>();
    conv3x3_kernel<<<dim3(36, 16, 1), 256>>>(x1, x2, w1, w2, w3, out, 1);
}

// round 5
// speedup vs baseline: 2.9203x; 2.4470x over previous
#include <cuda_runtime.h>
#include <cstdint>

#define NB   16
#define C    64
#define HWSZ 9216
#define CHW  589824
#define KK   576
#define NSLICE 4

// Scratch (static device arrays). Feature maps NHWC: [b][px][c].
__device__ float g_kf[NB * CHW];
__device__ float g_qf[NB * CHW];
__device__ float g_vf[NB * CHW];
__device__ float g_sc[NSLICE][NB * C * KK];
__device__ float g_w9s[3 * 9 * 64 * 64];   // [z][k9][cout][cin], tf32-rounded
__device__ float g_w9d[NB * 9 * 64 * 64];  // [b][k9][cout][cin], tf32-rounded

// tcgen05 is an arch-SPECIFIC feature: only emit it in the sm_103a/sm_100a
// device pass. The plain compute_103 PTX pass (harness forward-compat build)
// gets an empty kernel body; the driver loads the exact-match cubin on GB300.
#if defined(__CUDA_ARCH_FEAT_SM103_ALL) || defined(__CUDA_ARCH_FEAT_SM100_ALL) \
    || (defined(__CUDA_ARCH_SPECIFIC__) && (__CUDA_ARCH_SPECIFIC__ >= 1000))
#define HAS_TCGEN05 1
#else
#define HAS_TCGEN05 0
#endif

// ---------------- PTX helpers (arch-neutral) ----------------
__device__ __forceinline__ float tf32r(float x) {
    uint32_t u;
    asm("cvt.rna.tf32.f32 %0, %1;" : "=r"(u) : "f"(x));
    return __uint_as_float(u);
}

#if HAS_TCGEN05
__device__ __forceinline__ uint32_t smem_u32(const void* p) {
    uint32_t a;
    asm("{ .reg .u64 t; cvta.to.shared.u64 t, %1; cvt.u32.u64 %0, t; }"
        : "=r"(a) : "l"(p));
    return a;
}
__device__ __forceinline__ uint32_t elect_one() {
    uint32_t pred;
    asm volatile("{\n\t.reg .pred p;\n\telect.sync _|p, 0xFFFFFFFF;\n\t"
                 "selp.b32 %0, 1, 0, p;\n\t}" : "=r"(pred));
    return pred;
}

#define MBARRIER_INIT(addr, cnt) \
    asm volatile("mbarrier.init.shared.b64 [%0], %1;" :: "r"(addr), "r"(cnt) : "memory")
#define MBARRIER_INVAL(addr) \
    asm volatile("mbarrier.inval.shared.b64 [%0];" :: "r"(addr) : "memory")
#define MBARRIER_WAIT_PARITY(addr, par) do {                                   \
    uint32_t _m = (addr), _p = (par), _d;                                      \
    asm volatile("{\n\t.reg .pred p;\n\t"                                      \
        "mbarrier.try_wait.parity.acquire.cta.shared::cta.b64 p, [%1], %2;\n\t"\
        "selp.b32 %0, 1, 0, p;\n\t}" : "=r"(_d) : "r"(_m), "r"(_p) : "memory");\
    if (!_d) {                                                                 \
        asm volatile("{\n\t.reg .pred P1;\n\tWL%=:\n\t"                        \
        "mbarrier.try_wait.parity.acquire.cta.shared::cta.b64 P1, [%0], %1, 0x989680;\n\t" \
        "@P1 bra.uni WD%=;\n\tbra.uni WL%=;\n\tWD%=:\n\t}"                     \
        :: "r"(_m), "r"(_p) : "memory");                                       \
    } } while (0)

#define TCGEN05_ALLOC(res, n) \
    asm volatile("tcgen05.alloc.cta_group::1.sync.aligned.shared::cta.b32 [%0], %1;" \
                 :: "r"(res), "r"((uint32_t)(n)) : "memory")
#define TCGEN05_DEALLOC(t, n) \
    asm volatile("tcgen05.dealloc.cta_group::1.sync.aligned.b32 %0, %1;" :: "r"(t), "r"((uint32_t)(n)))
#define TCGEN05_RELINQ() \
    asm volatile("tcgen05.relinquish_alloc_permit.cta_group::1.sync.aligned;")
#define TCGEN05_COMMIT(mb) \
    asm volatile("tcgen05.commit.cta_group::1.mbarrier::arrive::one.shared::cluster.b64 [%0];" \
                 :: "r"(mb) : "memory")
#define TCGEN05_FENCE_AFTER()  asm volatile("tcgen05.fence::after_thread_sync;" ::: "memory")
#define TCGEN05_FENCE_BEFORE() asm volatile("tcgen05.fence::before_thread_sync;" ::: "memory")
#define TCGEN05_WAIT_LD()      asm volatile("tcgen05.wait::ld.sync.aligned;" ::: "memory")
#define FENCE_ASYNC_SHARED()   asm volatile("fence.proxy.async.shared::cta;" ::: "memory")

#define TCGEN05_LD_X32(r, ta) \
    asm volatile("tcgen05.ld.sync.aligned.32x32b.x32.b32 "                     \
        "{%0,%1,%2,%3,%4,%5,%6,%7,%8,%9,%10,%11,%12,%13,%14,%15,"             \
        "%16,%17,%18,%19,%20,%21,%22,%23,%24,%25,%26,%27,%28,%29,%30,%31}, [%32];" \
        : "=r"((r)[0]),"=r"((r)[1]),"=r"((r)[2]),"=r"((r)[3]),                 \
          "=r"((r)[4]),"=r"((r)[5]),"=r"((r)[6]),"=r"((r)[7]),                 \
          "=r"((r)[8]),"=r"((r)[9]),"=r"((r)[10]),"=r"((r)[11]),               \
          "=r"((r)[12]),"=r"((r)[13]),"=r"((r)[14]),"=r"((r)[15]),             \
          "=r"((r)[16]),"=r"((r)[17]),"=r"((r)[18]),"=r"((r)[19]),             \
          "=r"((r)[20]),"=r"((r)[21]),"=r"((r)[22]),"=r"((r)[23]),             \
          "=r"((r)[24]),"=r"((r)[25]),"=r"((r)[26]),"=r"((r)[27]),             \
          "=r"((r)[28]),"=r"((r)[29]),"=r"((r)[30]),"=r"((r)[31])              \
        : "r"(ta))

__device__ __forceinline__ void mma_tf32(uint32_t d, uint64_t a, uint64_t b,
                                         uint32_t idesc, uint32_t en) {
    asm volatile("{\n\t.reg .pred p;\n\tsetp.ne.u32 p, %5, 0;\n\t"
                 "tcgen05.mma.cta_group::1.kind::tf32 [%0], %1, %2, %3, {%4,%4,%4,%4}, p;\n\t}"
                 :: "r"(d), "l"(a), "l"(b), "r"(idesc), "r"(0u), "r"(en) : "memory");
}

// SW128 K-major descriptor (LBO=1, SBO=64), Blackwell version bit.
static __device__ __forceinline__ uint64_t mk_desc(uint32_t addr) {
    return ((uint64_t)2 << 61) | ((uint64_t)1 << 46) | ((uint64_t)64 << 32)
         | ((uint64_t)1 << 16) | (uint64_t)((addr >> 4) & 0x3FFF);
}
__device__ __forceinline__ uint32_t sw128(uint32_t off) { return off ^ ((off >> 3) & 0x70); }

// idesc: D=F32, a=TF32, b=TF32, K-major both, N=64, M=128
#define IDESC_TF32 ((1u<<4) | (2u<<7) | (2u<<10) | ((64u/8u)<<17) | ((128u/16u)<<24))
#endif  // HAS_TCGEN05

#define ABUF_BYTES 17408              // 136 rows * 128B (1024-aligned)
#define BREG_OFF   (4 * ABUF_BYTES)   // 69632
#define SMEM_DYN   (1024 + BREG_OFF + 9 * 8192)

// ---------------------------------------------------------------------------
// Tensor-core conv. Grid (12, 16, z). 128 threads.
// dyn=0: z in {0,1,2}: (x1,w9s[0])->g_kf, (x2,w9s[1])->g_qf, (x1,w9s[2])->g_vf
//        output NHWC.
// dyn=1: A=g_vf (NHWC), B=g_w9d[b], output NCHW to out.
// ---------------------------------------------------------------------------
__global__ void __launch_bounds__(128, 1)
conv_tc_kernel(const float* __restrict__ x1, const float* __restrict__ x2,
               float* __restrict__ out, int dyn)
{
#if HAS_TCGEN05
    extern __shared__ char smem[];
    __shared__ uint32_t s_tmem;
    __shared__ alignas(16) unsigned long long s_mbar[2];

    const int tid = threadIdx.x;
    const int wid = tid >> 5, lid = tid & 31;
    const int r0  = blockIdx.x * 8;
    const int b   = blockIdx.y;
    const int z   = blockIdx.z;

    uint32_t sm0 = smem_u32(smem);
    uint32_t Ab  = (sm0 + 1023) & ~1023u;
    uint32_t Bb  = Ab + BREG_OFF;
    char* Abp = smem + (Ab - sm0);
    char* Bbp = smem + (Bb - sm0);
    uint32_t mb[2] = { smem_u32(&s_mbar[0]), smem_u32(&s_mbar[1]) };

    if (wid == 0) TCGEN05_ALLOC(smem_u32(&s_tmem), 512);
    if (tid == 0) { MBARRIER_INIT(mb[0], 1); MBARRIER_INIT(mb[1], 1); }
    // zero constant halo rows (row 0 = col -1; rows 97..135) of all 4 A buffers
    for (int i = tid; i < 4 * 40 * 32; i += 128) {
        int buf = i / 1280, rr = i % 1280, row = rr >> 5, wd = rr & 31;
        int prow = (row == 0) ? 0 : (96 + row);
        *(float*)(Abp + buf * ABUF_BYTES + prow * 128 + wd * 4) = 0.f;
    }
    if (wid == 0) TCGEN05_RELINQ();
    __syncthreads();
    const uint32_t tmem = s_tmem;

    const float* xsrc = dyn ? nullptr : ((z == 1) ? x2 : x1);

    int ncommit = 0;
    for (int h = 0; h < 2; h++) {
        if (ncommit > 0) {
            int k = ncommit - 1;
            MBARRIER_WAIT_PARITY(mb[k & 1], (k >> 1) & 1);
        }
        // ---- load B: 9 shifts x 64 cout x 32 cin (tf32 already) ----
        #pragma unroll 4
        for (int it = 0; it < 36; it++) {
            int idx = it * 128 + tid;
            int k9 = idx >> 9, r2 = idx & 511, co = r2 >> 3, ci4 = r2 & 7;
            const float* src = dyn
                ? &g_w9d[(((size_t)b * 9 + k9) * 64 + co) * 64 + h * 32 + ci4 * 4]
                : &g_w9s[(((size_t)z * 9 + k9) * 64 + co) * 64 + h * 32 + ci4 * 4];
            float4 v = *(const float4*)src;
            *(float4*)(Bbp + k9 * 8192 + sw128(co * 128 + ci4 * 16)) = v;
        }
        // ---- A loader (one image row -> one buffer) ----
        auto load_a = [&](char* abuf, int ri) {
            bool valid = (ri >= 0) && (ri < 96);
            if (!dyn) {
                const float* src = xsrc + (size_t)b * CHW;
                #pragma unroll
                for (int it = 0; it < 6; it++) {
                    int idx = it * 128 + tid;
                    int cin = idx / 24, c4 = idx % 24;
                    float4 v = make_float4(0.f, 0.f, 0.f, 0.f);
                    if (valid)
                        v = *(const float4*)(src + (size_t)(h * 32 + cin) * HWSZ
                                             + ri * 96 + c4 * 4);
                    float vv[4] = {v.x, v.y, v.z, v.w};
                    #pragma unroll
                    for (int j = 0; j < 4; j++)
                        *(float*)(abuf + sw128((c4 * 4 + j + 1) * 128 + cin * 4))
                            = tf32r(vv[j]);
                }
            } else {
                const float* src = g_vf + (size_t)b * CHW;
                #pragma unroll
                for (int it = 0; it < 6; it++) {
                    int idx = it * 128 + tid;
                    int col = idx >> 3, ci4 = idx & 7;
                    float4 v = make_float4(0.f, 0.f, 0.f, 0.f);
                    if (valid)
                        v = *(const float4*)(src + (size_t)(ri * 96 + col) * 64
                                             + h * 32 + ci4 * 4);
                    float4 w4 = make_float4(tf32r(v.x), tf32r(v.y), tf32r(v.z), tf32r(v.w));
                    *(float4*)(abuf + sw128((col + 1) * 128 + ci4 * 16)) = w4;
                }
            }
        };
        // prologue: buffers 0,1,2 = image rows r0-1, r0, r0+1
        for (int i = 0; i < 3; i++) load_a(Abp + i * ABUF_BYTES, r0 - 1 + i);
        __syncthreads();
        FENCE_ASYNC_SHARED();

        for (int r = 0; r < 8; r++) {
            if (wid == 0 && elect_one()) {
                #pragma unroll
                for (int s = 0; s < 9; s++) {
                    int kh = s / 3, kw = s - kh * 3;
                    uint64_t ad = mk_desc(Ab + ((r + kh) & 3) * ABUF_BYTES + kw * 128);
                    uint64_t bd = mk_desc(Bb + s * 8192);
                    #pragma unroll
                    for (int ks = 0; ks < 4; ks++)
                        mma_tf32(tmem + r * 64, ad + ks * 2, bd + ks * 2,
                                 IDESC_TF32, (h | s | ks) != 0);
                }
                TCGEN05_COMMIT(mb[ncommit & 1]);
            }
            ncommit++;
            if (r < 7) {
                if (ncommit >= 2) {
                    int k = ncommit - 2;
                    MBARRIER_WAIT_PARITY(mb[k & 1], (k >> 1) & 1);
                }
                load_a(Abp + ((r + 3) & 3) * ABUF_BYTES, r0 + r + 2);
                __syncthreads();
                FENCE_ASYNC_SHARED();
            }
        }
    }
    { int k = ncommit - 1; MBARRIER_WAIT_PARITY(mb[k & 1], (k >> 1) & 1); }
    TCGEN05_FENCE_AFTER();

    // ---- epilogue: D[px 0..95][cout 0..63] per row ----
    if (wid < 3) {
        int px = wid * 32 + lid;
        for (int r = 0; r < 8; r++) {
            uint32_t d0[32], d1[32];
            TCGEN05_LD_X32(d0, tmem + r * 64);
            TCGEN05_LD_X32(d1, tmem + r * 64 + 32);
            TCGEN05_WAIT_LD();
            if (!dyn) {
                float* dst = ((z == 0) ? g_kf : (z == 1) ? g_qf : g_vf)
                           + ((size_t)b * HWSZ + (size_t)(r0 + r) * 96 + px) * 64;
                #pragma unroll
                for (int q = 0; q < 8; q++)
                    *(float4*)(dst + q * 4) = make_float4(
                        __uint_as_float(d0[q*4]),   __uint_as_float(d0[q*4+1]),
                        __uint_as_float(d0[q*4+2]), __uint_as_float(d0[q*4+3]));
                #pragma unroll
                for (int q = 0; q < 8; q++)
                    *(float4*)(dst + 32 + q * 4) = make_float4(
                        __uint_as_float(d1[q*4]),   __uint_as_float(d1[q*4+1]),
                        __uint_as_float(d1[q*4+2]), __uint_as_float(d1[q*4+3]));
            } else {
                float* dst = out + (size_t)b * CHW + (size_t)(r0 + r) * 96 + px;
                #pragma unroll
                for (int c = 0; c < 32; c++) dst[(size_t)c * HWSZ] = __uint_as_float(d0[c]);
                #pragma unroll
                for (int c = 0; c < 32; c++) dst[(size_t)(c + 32) * HWSZ] = __uint_as_float(d1[c]);
            }
        }
    }
    TCGEN05_FENCE_BEFORE();
    __syncthreads();
    if (tid == 0) { MBARRIER_INVAL(mb[0]); MBARRIER_INVAL(mb[1]); }
    __syncthreads();
    if (wid == 0) TCGEN05_DEALLOC(tmem, 512);
#endif  // HAS_TCGEN05
}

// ---------------------------------------------------------------------------
// Static-weight transpose + tf32 round: w9s[z][k][cout][cin]
// ---------------------------------------------------------------------------
__global__ void __launch_bounds__(256) prep_w9s_kernel(
    const float* __restrict__ w1, const float* __restrict__ w2,
    const float* __restrict__ w3)
{
    int idx = blockIdx.x * 256 + threadIdx.x;
    if (idx >= 3 * 9 * 4096) return;
    int z = idx / 36864, rem = idx - z * 36864;
    int k = rem >> 12, r2 = rem & 4095, co = r2 >> 6, ci = r2 & 63;
    const float* w = (z == 0) ? w1 : (z == 1) ? w2 : w3;
    g_w9s[idx] = tf32r(w[co * 576 + ci * 9 + k]);
}

// ---------------------------------------------------------------------------
// scores partials (NHWC inputs). Grid (9, 16, 4), block 256.
// ---------------------------------------------------------------------------
__global__ void __launch_bounds__(256) scores_kernel()
{
    const int k  = blockIdx.x, b = blockIdx.y, s = blockIdx.z;
    const int kh = k / 3, kw = k % 3;
    const float* kfb = g_kf + (size_t)b * CHW;
    const float* qfb = g_qf + (size_t)b * CHW;

    __shared__ float SK[32][68];
    __shared__ float SQ[32][68];

    const int tid = threadIdx.x;
    const int tc  = (tid & 15) << 2;
    const int td  = (tid >> 4) << 2;

    float acc[4][4] = {};
    for (int l0 = s * 256; l0 < s * 256 + 256; l0 += 32) {
        __syncthreads();
        #pragma unroll
        for (int it = 0; it < 8; it++) {
            int idx = tid + it * 256;           // 0..2047
            int li = idx >> 6, c = idx & 63;
            int l = l0 + li;
            int pix = (3 * (l >> 5) + kh) * 96 + 3 * (l & 31) + kw;
            SK[li][c] = kfb[(size_t)pix * 64 + c];
            SQ[li][c] = qfb[(size_t)pix * 64 + c];
        }
        __syncthreads();
        #pragma unroll 8
        for (int li = 0; li < 32; li++) {
            float4 av = *reinterpret_cast<const float4*>(&SK[li][tc]);
            float4 bv = *reinterpret_cast<const float4*>(&SQ[li][td]);
            float a[4]  = {av.x, av.y, av.z, av.w};
            float bb[4] = {bv.x, bv.y, bv.z, bv.w};
            #pragma unroll
            for (int i = 0; i < 4; i++)
                #pragma unroll
                for (int j = 0; j < 4; j++)
                    acc[i][j] = fmaf(a[i], bb[j], acc[i][j]);
        }
    }
    const float sc = 1.0f / 24.0f;
    #pragma unroll
    for (int j = 0; j < 4; j++) {
        float* ap = g_sc[s] + ((size_t)(b * C + td + j)) * KK + k;
        #pragma unroll
        for (int i = 0; i < 4; i++)
            ap[(tc + i) * 9] = acc[i][j] * sc;
    }
}

// ---------------------------------------------------------------------------
// Reduce partials + softmax; write dyn weights w9d[b][k][d][c] (tf32).
// One warp per (b,d) row.
// ---------------------------------------------------------------------------
__global__ void __launch_bounds__(256) softmax_kernel()
{
    const int row  = blockIdx.x * 8 + (threadIdx.x >> 5);   // b*64 + d
    const int lane = threadIdx.x & 31;
    const int b = row >> 6, d = row & 63;
    const size_t off = (size_t)row * KK;

    float v[18];
    float m = -3.4e38f;
    #pragma unroll
    for (int i = 0; i < 18; i++) {
        int idx = lane + i * 32;
        float t = g_sc[0][off + idx] + g_sc[1][off + idx]
                + g_sc[2][off + idx] + g_sc[3][off + idx];
        v[i] = t;
        m = fmaxf(m, t);
    }
    #pragma unroll
    for (int o = 16; o > 0; o >>= 1) m = fmaxf(m, __shfl_xor_sync(0xffffffffu, m, o));
    float ss = 0.f;
    #pragma unroll
    for (int i = 0; i < 18; i++) { v[i] = __expf(v[i] - m); ss += v[i]; }
    #pragma unroll
    for (int o = 16; o > 0; o >>= 1) ss += __shfl_xor_sync(0xffffffffu, ss, o);
    float inv = 1.0f / ss;
    #pragma unroll
    for (int i = 0; i < 18; i++) {
        int idx = lane + i * 32;           // idx = c*9 + k
        int c = idx / 9, k = idx - c * 9;
        g_w9d[(((size_t)b * 9 + k) * 64 + d) * 64 + c] = tf32r(v[i] * inv);
    }
}

extern "C" void kernel_launch(void* const* d_in, const int* in_sizes, int n_in,
                              void* d_out, int out_size)
{
    const float* x1 = (const float*)d_in[0];
    const float* x2 = (const float*)d_in[1];
    const float* w1 = (const float*)d_in[2];
    const float* w2 = (const float*)d_in[3];
    const float* w3 = (const float*)d_in[4];
    float* out = (float*)d_out;

    cudaFuncSetAttribute(conv_tc_kernel,
                         cudaFuncAttributeMaxDynamicSharedMemorySize, SMEM_DYN);

    prep_w9s_kernel<<<(3 * 9 * 4096 + 255) / 256, 256>>>(w1, w2, w3);
    conv_tc_kernel<<<dim3(12, 16, 3), 128, SMEM_DYN>>>(x1, x2, out, 0);
    scores_kernel<<<dim3(9, 16, NSLICE), 256>>>();
    softmax_kernel<<<128, 256>>>();
    conv_tc_kernel<<<dim3(12, 16, 1), 128, SMEM_DYN>>>(x1, x2, out, 1);
}

// round 6
// speedup vs baseline: 3.1618x; 1.0827x over previous
#include <cuda_runtime.h>
#include <cstdint>

#define NB   16
#define C    64
#define HWSZ 9216
#define CHW  589824
#define KK   576
#define NSLICE 8

// Scratch (static device arrays). Feature maps NHWC: [b][px][c].
__device__ float g_kf[NB * CHW];
__device__ float g_qf[NB * CHW];
__device__ float g_vf[NB * CHW];
__device__ float g_sc[NSLICE][NB * C * KK];
__device__ float g_w9s[3 * 9 * 64 * 64];   // [z][k9][cout][cin], tf32-rounded
__device__ float g_w9d[NB * 9 * 64 * 64];  // [b][k9][cout][cin], tf32-rounded

// tcgen05 is arch-SPECIFIC: only emit in the sm_103a/sm_100a pass.
#if defined(__CUDA_ARCH_FEAT_SM103_ALL) || defined(__CUDA_ARCH_FEAT_SM100_ALL) \
    || (defined(__CUDA_ARCH_SPECIFIC__) && (__CUDA_ARCH_SPECIFIC__ >= 1000))
#define HAS_TCGEN05 1
#else
#define HAS_TCGEN05 0
#endif

__device__ __forceinline__ float tf32r(float x) {
    uint32_t u;
    asm("cvt.rna.tf32.f32 %0, %1;" : "=r"(u) : "f"(x));
    return __uint_as_float(u);
}

#if HAS_TCGEN05
__device__ __forceinline__ uint32_t smem_u32(const void* p) {
    uint32_t a;
    asm("{ .reg .u64 t; cvta.to.shared.u64 t, %1; cvt.u32.u64 %0, t; }"
        : "=r"(a) : "l"(p));
    return a;
}
__device__ __forceinline__ uint32_t elect_one() {
    uint32_t pred;
    asm volatile("{\n\t.reg .pred p;\n\telect.sync _|p, 0xFFFFFFFF;\n\t"
                 "selp.b32 %0, 1, 0, p;\n\t}" : "=r"(pred));
    return pred;
}

#define MBARRIER_INIT(addr, cnt) \
    asm volatile("mbarrier.init.shared.b64 [%0], %1;" :: "r"(addr), "r"(cnt) : "memory")
#define MBARRIER_INVAL(addr) \
    asm volatile("mbarrier.inval.shared.b64 [%0];" :: "r"(addr) : "memory")
#define MBARRIER_WAIT_PARITY(addr, par) do {                                   \
    uint32_t _m = (addr), _p = (par), _d;                                      \
    asm volatile("{\n\t.reg .pred p;\n\t"                                      \
        "mbarrier.try_wait.parity.acquire.cta.shared::cta.b64 p, [%1], %2;\n\t"\
        "selp.b32 %0, 1, 0, p;\n\t}" : "=r"(_d) : "r"(_m), "r"(_p) : "memory");\
    if (!_d) {                                                                 \
        asm volatile("{\n\t.reg .pred P1;\n\tWL%=:\n\t"                        \
        "mbarrier.try_wait.parity.acquire.cta.shared::cta.b64 P1, [%0], %1, 0x989680;\n\t" \
        "@P1 bra.uni WD%=;\n\tbra.uni WL%=;\n\tWD%=:\n\t}"                     \
        :: "r"(_m), "r"(_p) : "memory");                                       \
    } } while (0)

#define TCGEN05_ALLOC(res, n) \
    asm volatile("tcgen05.alloc.cta_group::1.sync.aligned.shared::cta.b32 [%0], %1;" \
                 :: "r"(res), "r"((uint32_t)(n)) : "memory")
#define TCGEN05_DEALLOC(t, n) \
    asm volatile("tcgen05.dealloc.cta_group::1.sync.aligned.b32 %0, %1;" :: "r"(t), "r"((uint32_t)(n)))
#define TCGEN05_RELINQ() \
    asm volatile("tcgen05.relinquish_alloc_permit.cta_group::1.sync.aligned;")
#define TCGEN05_COMMIT(mb) \
    asm volatile("tcgen05.commit.cta_group::1.mbarrier::arrive::one.shared::cluster.b64 [%0];" \
                 :: "r"(mb) : "memory")
#define TCGEN05_FENCE_AFTER()  asm volatile("tcgen05.fence::after_thread_sync;" ::: "memory")
#define TCGEN05_FENCE_BEFORE() asm volatile("tcgen05.fence::before_thread_sync;" ::: "memory")
#define TCGEN05_WAIT_LD()      asm volatile("tcgen05.wait::ld.sync.aligned;" ::: "memory")
#define FENCE_ASYNC_SHARED()   asm volatile("fence.proxy.async.shared::cta;" ::: "memory")

#define TCGEN05_LD_X32(r, ta) \
    asm volatile("tcgen05.ld.sync.aligned.32x32b.x32.b32 "                     \
        "{%0,%1,%2,%3,%4,%5,%6,%7,%8,%9,%10,%11,%12,%13,%14,%15,"             \
        "%16,%17,%18,%19,%20,%21,%22,%23,%24,%25,%26,%27,%28,%29,%30,%31}, [%32];" \
        : "=r"((r)[0]),"=r"((r)[1]),"=r"((r)[2]),"=r"((r)[3]),                 \
          "=r"((r)[4]),"=r"((r)[5]),"=r"((r)[6]),"=r"((r)[7]),                 \
          "=r"((r)[8]),"=r"((r)[9]),"=r"((r)[10]),"=r"((r)[11]),               \
          "=r"((r)[12]),"=r"((r)[13]),"=r"((r)[14]),"=r"((r)[15]),             \
          "=r"((r)[16]),"=r"((r)[17]),"=r"((r)[18]),"=r"((r)[19]),             \
          "=r"((r)[20]),"=r"((r)[21]),"=r"((r)[22]),"=r"((r)[23]),             \
          "=r"((r)[24]),"=r"((r)[25]),"=r"((r)[26]),"=r"((r)[27]),             \
          "=r"((r)[28]),"=r"((r)[29]),"=r"((r)[30]),"=r"((r)[31])              \
        : "r"(ta))

__device__ __forceinline__ void mma_tf32(uint32_t d, uint64_t a, uint64_t b,
                                         uint32_t idesc, uint32_t en) {
    asm volatile("{\n\t.reg .pred p;\n\tsetp.ne.u32 p, %5, 0;\n\t"
                 "tcgen05.mma.cta_group::1.kind::tf32 [%0], %1, %2, %3, {%4,%4,%4,%4}, p;\n\t}"
                 :: "r"(d), "l"(a), "l"(b), "r"(idesc), "r"(0u), "r"(en) : "memory");
}

static __device__ __forceinline__ uint64_t mk_desc(uint32_t addr) {
    return ((uint64_t)2 << 61) | ((uint64_t)1 << 46) | ((uint64_t)64 << 32)
         | ((uint64_t)1 << 16) | (uint64_t)((addr >> 4) & 0x3FFF);
}
__device__ __forceinline__ uint32_t sw128(uint32_t off) { return off ^ ((off >> 3) & 0x70); }

// idesc: D=F32, a=TF32, b=TF32, K-major both, N=64, M=128
#define IDESC_TF32 ((1u<<4) | (2u<<7) | (2u<<10) | ((64u/8u)<<17) | ((128u/16u)<<24))
#endif  // HAS_TCGEN05

#define NBUF       6
#define ABUF_BYTES 16384              // 128 rows * 128B
#define BREG_OFF   (NBUF * ABUF_BYTES)
#define SMEM_DYN   (1024 + BREG_OFF + 9 * 8192)

// ---------------------------------------------------------------------------
// Tensor-core conv. Grid (12, 16, z). 256 threads.
// ---------------------------------------------------------------------------
__global__ void __launch_bounds__(256, 1)
conv_tc_kernel(const float* __restrict__ x1, const float* __restrict__ x2,
               float* __restrict__ out, int dyn)
{
#if HAS_TCGEN05
    extern __shared__ char smem[];
    __shared__ uint32_t s_tmem;
    __shared__ alignas(16) unsigned long long s_mbar[4];

    const int tid = threadIdx.x;
    const int wid = tid >> 5, lid = tid & 31;
    const int r0  = blockIdx.x * 8;
    const int b   = blockIdx.y;
    const int z   = blockIdx.z;

    uint32_t sm0 = smem_u32(smem);
    uint32_t Ab  = (sm0 + 1023) & ~1023u;
    uint32_t Bb  = Ab + BREG_OFF;
    char* Abp = smem + (Ab - sm0);
    char* Bbp = smem + (Bb - sm0);
    uint32_t mb[4] = { smem_u32(&s_mbar[0]), smem_u32(&s_mbar[1]),
                       smem_u32(&s_mbar[2]), smem_u32(&s_mbar[3]) };

    if (wid == 0) TCGEN05_ALLOC(smem_u32(&s_tmem), 512);
    if (tid < 4) MBARRIER_INIT(mb[tid], 1);
    // zero constant halo rows (row 0 = col -1; rows 97..127) of all buffers
    for (int i = tid; i < NBUF * 32 * 32; i += 256) {
        int buf = i >> 10, rr = i & 1023, row = rr >> 5, wd = rr & 31;
        int prow = (row == 0) ? 0 : (96 + row);
        *(float*)(Abp + buf * ABUF_BYTES + prow * 128 + wd * 4) = 0.f;
    }
    if (wid == 0) TCGEN05_RELINQ();
    __syncthreads();
    const uint32_t tmem = s_tmem;

    const float* xsrc = dyn ? nullptr : ((z == 1) ? x2 : x1);

    int ncommit = 0;
    for (int h = 0; h < 2; h++) {
        if (ncommit > 0) {       // B tile reused: drain all prior MMAs
            int k = ncommit - 1;
            MBARRIER_WAIT_PARITY(mb[k & 3], (k >> 2) & 1);
        }
        // ---- load B: 9 shifts x 64 cout x 32 cin ----
        #pragma unroll 4
        for (int it = 0; it < 18; it++) {
            int idx = it * 256 + tid;
            int k9 = idx >> 9, r2 = idx & 511, co = r2 >> 3, ci4 = r2 & 7;
            const float* src = dyn
                ? &g_w9d[(((size_t)b * 9 + k9) * 64 + co) * 64 + h * 32 + ci4 * 4]
                : &g_w9s[(((size_t)z * 9 + k9) * 64 + co) * 64 + h * 32 + ci4 * 4];
            float4 v = *(const float4*)src;
            *(float4*)(Bbp + k9 * 8192 + sw128(co * 128 + ci4 * 16)) = v;
        }
        // ---- A loader: one image row -> one buffer (256 threads) ----
        auto load_a = [&](char* abuf, int ri) {
            bool valid = (ri >= 0) && (ri < 96);
            if (!dyn) {
                const float* src = xsrc + (size_t)b * CHW;
                #pragma unroll
                for (int it = 0; it < 3; it++) {
                    int idx = it * 256 + tid;
                    int cin = idx / 24, c4 = idx % 24;
                    float4 v = make_float4(0.f, 0.f, 0.f, 0.f);
                    if (valid)
                        v = *(const float4*)(src + (size_t)(h * 32 + cin) * HWSZ
                                             + ri * 96 + c4 * 4);
                    float vv[4] = {v.x, v.y, v.z, v.w};
                    #pragma unroll
                    for (int j = 0; j < 4; j++)
                        *(float*)(abuf + sw128((c4 * 4 + j + 1) * 128 + cin * 4))
                            = tf32r(vv[j]);
                }
            } else {
                const float* src = g_vf + (size_t)b * CHW;
                #pragma unroll
                for (int it = 0; it < 3; it++) {
                    int idx = it * 256 + tid;
                    int col = idx >> 3, ci4 = idx & 7;
                    float4 v = make_float4(0.f, 0.f, 0.f, 0.f);
                    if (valid)
                        v = *(const float4*)(src + (size_t)(ri * 96 + col) * 64
                                             + h * 32 + ci4 * 4);
                    float4 w4 = make_float4(tf32r(v.x), tf32r(v.y), tf32r(v.z), tf32r(v.w));
                    *(float4*)(abuf + sw128((col + 1) * 128 + ci4 * 16)) = w4;
                }
            }
        };
        // prologue: buffers 0,1,2 = image rows r0-1, r0, r0+1
        for (int i = 0; i < 3; i++) load_a(Abp + i * ABUF_BYTES, r0 - 1 + i);
        __syncthreads();
        FENCE_ASYNC_SHARED();

        for (int r = 0; r < 8; r++) {
            if (wid == 0 && elect_one()) {
                #pragma unroll
                for (int s = 0; s < 9; s++) {
                    int kh = s / 3, kw = s - kh * 3;
                    int buf = (r + kh) % NBUF;
                    uint64_t ad = mk_desc(Ab + buf * ABUF_BYTES + kw * 128);
                    uint64_t bd = mk_desc(Bb + s * 8192);
                    #pragma unroll
                    for (int ks = 0; ks < 4; ks++)
                        mma_tf32(tmem + r * 64, ad + ks * 2, bd + ks * 2,
                                 IDESC_TF32, (h | s | ks) != 0);
                }
                TCGEN05_COMMIT(mb[ncommit & 3]);
            }
            ncommit++;
            if (r < 7) {
                // buffer (r+3)%NBUF last read by pass r-3 -> wait it (3 deep)
                if (r >= 3) {
                    int k = ncommit - 4;
                    MBARRIER_WAIT_PARITY(mb[k & 3], (k >> 2) & 1);
                }
                load_a(Abp + ((r + 3) % NBUF) * ABUF_BYTES, r0 + r + 2);
                __syncthreads();
                FENCE_ASYNC_SHARED();
            }
        }
    }
    { int k = ncommit - 1; MBARRIER_WAIT_PARITY(mb[k & 3], (k >> 2) & 1); }
    TCGEN05_FENCE_AFTER();

    // ---- epilogue: 6 warps; warps 0-2 cols 0..31, warps 4-6 cols 32..63 ----
    if ((wid & 3) < 3) {
        int half = wid >> 2;            // 0 or 1
        int px   = (wid & 3) * 32 + lid;
        for (int r = 0; r < 8; r++) {
            uint32_t d0[32];
            TCGEN05_LD_X32(d0, tmem + r * 64 + half * 32);
            TCGEN05_WAIT_LD();
            if (!dyn) {
                float* dst = ((z == 0) ? g_kf : (z == 1) ? g_qf : g_vf)
                           + ((size_t)b * HWSZ + (size_t)(r0 + r) * 96 + px) * 64
                           + half * 32;
                #pragma unroll
                for (int q = 0; q < 8; q++)
                    *(float4*)(dst + q * 4) = make_float4(
                        __uint_as_float(d0[q*4]),   __uint_as_float(d0[q*4+1]),
                        __uint_as_float(d0[q*4+2]), __uint_as_float(d0[q*4+3]));
            } else {
                float* dst = out + (size_t)b * CHW + (size_t)(r0 + r) * 96 + px
                           + (size_t)half * 32 * HWSZ;
                #pragma unroll
                for (int c = 0; c < 32; c++)
                    dst[(size_t)c * HWSZ] = __uint_as_float(d0[c]);
            }
        }
    }
    TCGEN05_FENCE_BEFORE();
    __syncthreads();
    if (tid < 4) MBARRIER_INVAL(mb[tid]);
    __syncthreads();
    if (wid == 0) TCGEN05_DEALLOC(tmem, 512);
#endif  // HAS_TCGEN05
}

// ---------------------------------------------------------------------------
// Static-weight transpose + tf32 round: w9s[z][k][cout][cin]
// ---------------------------------------------------------------------------
__global__ void __launch_bounds__(256) prep_w9s_kernel(
    const float* __restrict__ w1, const float* __restrict__ w2,
    const float* __restrict__ w3)
{
    int idx = blockIdx.x * 256 + threadIdx.x;
    if (idx >= 3 * 9 * 4096) return;
    int z = idx / 36864, rem = idx - z * 36864;
    int k = rem >> 12, r2 = rem & 4095, co = r2 >> 6, ci = r2 & 63;
    const float* w = (z == 0) ? w1 : (z == 1) ? w2 : w3;
    g_w9s[idx] = tf32r(w[co * 576 + ci * 9 + k]);
}

// ---------------------------------------------------------------------------
// scores partials (NHWC). Grid (9, 16, NSLICE), block 256. 128 L per slice.
// ---------------------------------------------------------------------------
__global__ void __launch_bounds__(256) scores_kernel()
{
    const int k  = blockIdx.x, b = blockIdx.y, s = blockIdx.z;
    const int kh = k / 3, kw = k % 3;
    const float* kfb = g_kf + (size_t)b * CHW;
    const float* qfb = g_qf + (size_t)b * CHW;

    __shared__ float SK[32][68];
    __shared__ float SQ[32][68];

    const int tid = threadIdx.x;
    const int tc  = (tid & 15) << 2;
    const int td  = (tid >> 4) << 2;

    float acc[4][4] = {};
    for (int l0 = s * 128; l0 < s * 128 + 128; l0 += 32) {
        __syncthreads();
        #pragma unroll
        for (int it = 0; it < 8; it++) {
            int idx = tid + it * 256;           // 0..2047
            int li = idx >> 6, c = idx & 63;
            int l = l0 + li;
            int pix = (3 * (l >> 5) + kh) * 96 + 3 * (l & 31) + kw;
            SK[li][c] = kfb[(size_t)pix * 64 + c];
            SQ[li][c] = qfb[(size_t)pix * 64 + c];
        }
        __syncthreads();
        #pragma unroll 8
        for (int li = 0; li < 32; li++) {
            float4 av = *reinterpret_cast<const float4*>(&SK[li][tc]);
            float4 bv = *reinterpret_cast<const float4*>(&SQ[li][td]);
            float a[4]  = {av.x, av.y, av.z, av.w};
            float bb[4] = {bv.x, bv.y, bv.z, bv.w};
            #pragma unroll
            for (int i = 0; i < 4; i++)
                #pragma unroll
                for (int j = 0; j < 4; j++)
                    acc[i][j] = fmaf(a[i], bb[j], acc[i][j]);
        }
    }
    const float sc = 1.0f / 24.0f;
    #pragma unroll
    for (int j = 0; j < 4; j++) {
        float* ap = g_sc[s] + ((size_t)(b * C + td + j)) * KK + k;
        #pragma unroll
        for (int i = 0; i < 4; i++)
            ap[(tc + i) * 9] = acc[i][j] * sc;
    }
}

// ---------------------------------------------------------------------------
// Reduce partials + softmax; write dyn weights w9d[b][k][d][c] (tf32).
// ---------------------------------------------------------------------------
__global__ void __launch_bounds__(256) softmax_kernel()
{
    const int row  = blockIdx.x * 8 + (threadIdx.x >> 5);   // b*64 + d
    const int lane = threadIdx.x & 31;
    const int b = row >> 6, d = row & 63;
    const size_t off = (size_t)row * KK;

    float v[18];
    float m = -3.4e38f;
    #pragma unroll
    for (int i = 0; i < 18; i++) {
        int idx = lane + i * 32;
        float t = 0.f;
        #pragma unroll
        for (int s = 0; s < NSLICE; s++) t += g_sc[s][off + idx];
        v[i] = t;
        m = fmaxf(m, t);
    }
    #pragma unroll
    for (int o = 16; o > 0; o >>= 1) m = fmaxf(m, __shfl_xor_sync(0xffffffffu, m, o));
    float ss = 0.f;
    #pragma unroll
    for (int i = 0; i < 18; i++) { v[i] = __expf(v[i] - m); ss += v[i]; }
    #pragma unroll
    for (int o = 16; o > 0; o >>= 1) ss += __shfl_xor_sync(0xffffffffu, ss, o);
    float inv = 1.0f / ss;
    #pragma unroll
    for (int i = 0; i < 18; i++) {
        int idx = lane + i * 32;           // idx = c*9 + k
        int c = idx / 9, k = idx - c * 9;
        g_w9d[(((size_t)b * 9 + k) * 64 + d) * 64 + c] = tf32r(v[i] * inv);
    }
}

extern "C" void kernel_launch(void* const* d_in, const int* in_sizes, int n_in,
                              void* d_out, int out_size)
{
    const float* x1 = (const float*)d_in[0];
    const float* x2 = (const float*)d_in[1];
    const float* w1 = (const float*)d_in[2];
    const float* w2 = (const float*)d_in[3];
    const float* w3 = (const float*)d_in[4];
    float* out = (float*)d_out;

    cudaFuncSetAttribute(conv_tc_kernel,
                         cudaFuncAttributeMaxDynamicSharedMemorySize, SMEM_DYN);

    prep_w9s_kernel<<<(3 * 9 * 4096 + 255) / 256, 256>>>(w1, w2, w3);
    conv_tc_kernel<<<dim3(12, 16, 3), 256, SMEM_DYN>>>(x1, x2, out, 0);
    scores_kernel<<<dim3(9, 16, NSLICE), 256>>>();
    softmax_kernel<<<128, 256>>>();
    conv_tc_kernel<<<dim3(12, 16, 1), 256, SMEM_DYN>>>(x1, x2, out, 1);
}